// round 16
// baseline (speedup 1.0000x reference)
#include <cuda_runtime.h>
#include <cuda_bf16.h>

#define BATCH 16
#define NPTS  1024
#define CDIM  64

// -------- scratch (__device__ globals, allocation-free rule) --------
__device__ float    g_r[BATCH * NPTS * CDIM];   // x@W_root + b_rel (fp32)
__device__ float    g_yT[BATCH * CDIM * NPTS];  // (x@W_rel)^T, tf32, sigma-permuted j
__device__ unsigned g_flag[BATCH * 16];         // per-j-tile ready flags (self-resetting)
__device__ unsigned g_done[BATCH];              // per-batch consume counters

// ===================== helpers =====================
__device__ __forceinline__ unsigned smem_u32(const void* p) {
    unsigned a;
    asm("{ .reg .u64 t; cvta.to.shared.u64 t, %1; cvt.u32.u64 %0, t; }"
        : "=r"(a) : "l"(p));
    return a;
}
#define CP_ASYNC16(dst, src) \
    asm volatile("cp.async.cg.shared.global [%0], [%1], 16;" :: "r"(dst), "l"(src))
#define CP_COMMIT()  asm volatile("cp.async.commit_group;" ::: "memory")
#define STS128F(addr, r0, r1, r2, r3) \
    asm volatile("st.shared.v4.f32 [%0], {%1,%2,%3,%4};" \
                 :: "r"(addr), "f"(r0), "f"(r1), "f"(r2), "f"(r3) : "memory")
__device__ __forceinline__ void sts_f(unsigned a, float v) {
    asm volatile("st.shared.f32 [%0], %1;" :: "r"(a), "f"(v) : "memory");
}
__device__ __forceinline__ float lds_f(unsigned a) {
    float r;
    asm volatile("ld.shared.f32 %0, [%1];" : "=f"(r) : "r"(a));
    return r;
}
__device__ __forceinline__ unsigned lds_u(unsigned a) {
    unsigned r;
    asm volatile("ld.shared.b32 %0, [%1];" : "=r"(r) : "r"(a));
    return r;
}
__device__ __forceinline__ uint2 lds_u64(unsigned a) {
    uint2 r;
    asm volatile("ld.shared.v2.b32 {%0,%1}, [%2];" : "=r"(r.x), "=r"(r.y) : "r"(a));
    return r;
}
__device__ __forceinline__ float4 lds128f(unsigned a) {
    float4 r;
    asm volatile("ld.shared.v4.f32 {%0,%1,%2,%3}, [%4];"
                 : "=f"(r.x), "=f"(r.y), "=f"(r.z), "=f"(r.w) : "r"(a));
    return r;
}
__device__ __forceinline__ float tf32r(float x) {
    unsigned u;
    asm("cvt.rna.tf32.f32 %0, %1;" : "=r"(u) : "f"(x));
    return __uint_as_float(u);
}
__device__ __forceinline__ void mma_tf32(float* d, const unsigned* a,
                                         unsigned b0, unsigned b1) {
    asm volatile("mma.sync.aligned.m16n8k8.row.col.f32.tf32.tf32.f32 "
                 "{%0,%1,%2,%3}, {%4,%5,%6,%7}, {%8,%9}, {%0,%1,%2,%3};"
                 : "+f"(d[0]), "+f"(d[1]), "+f"(d[2]), "+f"(d[3])
                 : "r"(a[0]), "r"(a[1]), "r"(a[2]), "r"(a[3]), "r"(b0), "r"(b1));
}
__device__ __forceinline__ void flag_wait(const unsigned* p) {
    unsigned v;
    do {
        asm volatile("ld.global.acquire.gpu.b32 %0, [%1];" : "=r"(v) : "l"(p) : "memory");
        if (!v) __nanosleep(64);
    } while (!v);
}

// ===================== layout =====================
#define S1_XH  0
#define S1_XL  17408
#define S1_WRH 34816
#define S1_WRL 52224
#define S1_WOH 69632
#define NCHUNK   16
#define ROWB     288
#define A_ST(t)  (((t) & 1) * 18432)
#define B_ST(t)  (36864 + ((t) % 3) * 18432)
#define LUT_OFF  92160
#define SMEM_DYN 92192

__device__ __forceinline__ void issue_B(unsigned sbp, int j0,
                                        const float* __restrict__ yT_b, int tid) {
#pragma unroll
    for (int v = 0; v < 2; v++) {
        const int idx  = tid + v * 512;
        const int row  = idx >> 4;
        const int slot = idx & 15;
        CP_ASYNC16(sbp + (unsigned)row * ROWB + slot * 16,
                   yT_b + ((long)row << 10) + j0 + slot * 4);
    }
    CP_COMMIT();
}

// ===================== fused kernel =====================
__global__ __launch_bounds__(512, 2) void fused_kernel(
    const float* __restrict__ x, const float* __restrict__ W_rel,
    const float* __restrict__ b_rel, const float* __restrict__ W_root,
    const float* __restrict__ adj, const int* __restrict__ ea,
    const float* __restrict__ w_edge, float* __restrict__ out)
{
    extern __shared__ char smem_raw[];
    const unsigned sb = smem_u32(smem_raw);
    const int tid = threadIdx.x, lane = tid & 31, wid = tid >> 5;
    const int b  = blockIdx.x >> 4;
    const int it = blockIdx.x & 15;
    const int i0 = it * 64;
    const int row0 = b * NPTS + i0;

    // ================= STAGE 1 (this CTA's 64 rows) =================
    {
        const int wi = wid & 3, wn = wid >> 2;

        {
            const int r = tid >> 3, ch = (tid & 7) * 8;
            const float* src = x + (long)(row0 + r) * 64 + ch;
            const unsigned dh = sb + S1_XH + (unsigned)r * 272 + (unsigned)ch * 4;
#pragma unroll
            for (int q = 0; q < 2; q++) {
                float4 v = __ldg((const float4*)(src + q * 4));
                float hx = tf32r(v.x), hy = tf32r(v.y), hz = tf32r(v.z), hw = tf32r(v.w);
                STS128F(dh + q * 16, hx, hy, hz, hw);
                STS128F(dh + 17408 + q * 16, tf32r(v.x - hx), tf32r(v.y - hy),
                                              tf32r(v.z - hz), tf32r(v.w - hw));
            }
        }
#pragma unroll
        for (int i = 0; i < 8; i++) {
            const int idx = i * 512 + tid;
            const int k = idx >> 6, n = idx & 63;
            const float vr = __ldg(W_rel + idx);
            const float vo = __ldg(W_root + idx);
            const float hr = tf32r(vr);
            const unsigned ad = sb + (unsigned)n * 272 + (unsigned)k * 4;
            sts_f(ad + S1_WRH, hr);
            sts_f(ad + S1_WRL, tf32r(vr - hr));
            sts_f(ad + S1_WOH, tf32r(vo));
        }
        __syncthreads();

        const int gid = lane >> 2, tig = lane & 3;
        const unsigned aoff = sb + (unsigned)(wi * 16 + gid) * 272 + (unsigned)tig * 4;
        const unsigned bnb  = (unsigned)(wn * 16 + gid) * 272 + (unsigned)tig * 4;

        float acc[2][4] = {};
#pragma unroll
        for (int ks = 0; ks < 8; ks++) {
            const unsigned kb = (unsigned)ks * 32;
            unsigned ah[4], al[4];
            ah[0] = lds_u(aoff + kb);            ah[1] = lds_u(aoff + kb + 8 * 272);
            ah[2] = lds_u(aoff + kb + 16);       ah[3] = lds_u(aoff + kb + 8 * 272 + 16);
            al[0] = lds_u(aoff + 17408 + kb);    al[1] = lds_u(aoff + 17408 + kb + 8 * 272);
            al[2] = lds_u(aoff + 17408 + kb + 16); al[3] = lds_u(aoff + 17408 + kb + 8 * 272 + 16);
#pragma unroll
            for (int nf = 0; nf < 2; nf++) {
                const unsigned bo = sb + bnb + (unsigned)nf * 2176 + kb;
                const unsigned bh0 = lds_u(bo + S1_WRH), bh1 = lds_u(bo + S1_WRH + 16);
                const unsigned bl0 = lds_u(bo + S1_WRL), bl1 = lds_u(bo + S1_WRL + 16);
                mma_tf32(acc[nf], ah, bh0, bh1);
                mma_tf32(acc[nf], al, bh0, bh1);
                mma_tf32(acc[nf], ah, bl0, bl1);
            }
        }
        __syncthreads();

#pragma unroll
        for (int nf = 0; nf < 2; nf++)
#pragma unroll
            for (int q = 0; q < 4; q++) {
                const int c = wn * 16 + nf * 8 + tig * 2 + (q & 1);
                const int j = wi * 16 + gid + (q >> 1) * 8;
                const int jp = (j & ~7) | (((j & 3) << 1) | ((j >> 2) & 1));
                sts_f(sb + S1_XL + (unsigned)c * 272 + (unsigned)jp * 4, tf32r(acc[nf][q]));
            }

        float acc2[2][4] = {};
#pragma unroll
        for (int ks = 0; ks < 8; ks++) {
            const unsigned kb = (unsigned)ks * 32;
            unsigned ah[4];
            ah[0] = lds_u(aoff + kb);      ah[1] = lds_u(aoff + kb + 8 * 272);
            ah[2] = lds_u(aoff + kb + 16); ah[3] = lds_u(aoff + kb + 8 * 272 + 16);
#pragma unroll
            for (int nf = 0; nf < 2; nf++) {
                const unsigned bo = sb + S1_WOH + bnb + (unsigned)nf * 2176 + kb;
                mma_tf32(acc2[nf], ah, lds_u(bo), lds_u(bo + 16));
            }
        }
        __syncthreads();

        {
            const int c = tid >> 3, jh = (tid & 7) * 8;
            float* dst = g_yT + ((long)(b * 64 + c) << 10) + i0 + jh;
            const unsigned sa = sb + S1_XL + (unsigned)c * 272 + (unsigned)jh * 4;
#pragma unroll
            for (int q = 0; q < 2; q++) {
                float4 v = lds128f(sa + q * 16);
                *(float4*)(dst + q * 4) = v;
            }
        }
#pragma unroll
        for (int nf = 0; nf < 2; nf++) {
            const int col = wn * 16 + nf * 8 + tig * 2;
            const int grow = row0 + wi * 16 + gid;
            const float2 rb = *(const float2*)(b_rel + col);
            float2 o0, o1;
            o0.x = acc2[nf][0] + rb.x; o0.y = acc2[nf][1] + rb.y;
            o1.x = acc2[nf][2] + rb.x; o1.y = acc2[nf][3] + rb.y;
            *(float2*)&g_r[(long)grow * 64 + col] = o0;
            *(float2*)&g_r[(long)(grow + 8) * 64 + col] = o1;
        }
    }

    // ---- publish own y^T slice, set ready flag (before ANY wait) ----
    const unsigned lut = sb + LUT_OFF;
    if (tid < 4) sts_f(lut + tid * 4, __ldg(w_edge + tid));
    __threadfence();
    __syncthreads();
    if (tid == 0)
        asm volatile("st.global.release.gpu.b32 [%0], %1;"
                     :: "l"(&g_flag[b * 16 + it]), "r"(1u) : "memory");

    // ================= STAGE 2 (rotated chunks: jt = (it+t) & 15) =================
    {
        const int wi = wid & 3, wn = wid >> 2;

        const float* adj_b = adj + ((long)b << 20);
        const int*   ea_b  = ea  + ((long)b << 20);
        const float* yT_b  = g_yT + ((long)(b * 64) << 10);
        const unsigned* flags = &g_flag[b * 16];

        const int  arow = tid >> 3;
        const int  ac0  = (tid & 7) << 3;
        const long rowbase = (long)(i0 + arow) * NPTS + ac0;

        const unsigned aoff = (unsigned)(wi * 16 + (lane >> 2)) * ROWB +
                              (unsigned)(lane & 3) * 8;
        const unsigned boff = (unsigned)(wn * 16 + (lane >> 2)) * ROWB +
                              (unsigned)(lane & 3) * 8;

        float acc[2][4] = {};
        float4 pa[2]; int4 pe[2];

        // chunk 0 = own tile: ready by construction (flag already set by us)
        issue_B(sb + B_ST(0), i0, yT_b, tid);
        // chunk 1 tile: wait its producer
        if (tid == 0) flag_wait(&flags[(it + 1) & 15]);
        __syncthreads();
        issue_B(sb + B_ST(1), ((it + 1) & 15) << 6, yT_b, tid);

#pragma unroll
        for (int q = 0; q < 2; q++) {
            pa[q] = __ldg((const float4*)(adj_b + rowbase + i0 + q * 4));
            pe[q] = __ldg((const int4*)(ea_b + rowbase + i0 + q * 4));
        }
        {
            float v[8];
            const int e[8] = {pe[0].x, pe[0].y, pe[0].z, pe[0].w,
                              pe[1].x, pe[1].y, pe[1].z, pe[1].w};
            const float a[8] = {pa[0].x, pa[0].y, pa[0].z, pa[0].w,
                                pa[1].x, pa[1].y, pa[1].z, pa[1].w};
#pragma unroll
            for (int p = 0; p < 8; p++)
                v[p] = tf32r(a[p] * lds_f(lut + ((unsigned)e[p] << 2)));
            const unsigned o0 = sb + A_ST(0) + (unsigned)arow * ROWB + (unsigned)ac0 * 4;
            STS128F(o0,      v[0], v[4], v[1], v[5]);
            STS128F(o0 + 16, v[2], v[6], v[3], v[7]);
        }
        {
            const long src = rowbase + (((it + 1) & 15) << 6);
#pragma unroll
            for (int q = 0; q < 2; q++) {
                pa[q] = __ldg((const float4*)(adj_b + src + q * 4));
                pe[q] = __ldg((const int4*)(ea_b + src + q * 4));
            }
        }

#pragma unroll 1
        for (int t = 0; t < NCHUNK; t++) {
            if (t < NCHUNK - 1) asm volatile("cp.async.wait_group 1;" ::: "memory");
            else                asm volatile("cp.async.wait_group 0;" ::: "memory");
            if (t + 2 < NCHUNK && tid == 0)
                flag_wait(&flags[(it + t + 2) & 15]);
            __syncthreads();
            if (t + 2 < NCHUNK)
                issue_B(sb + B_ST(t + 2), ((it + t + 2) & 15) << 6, yT_b, tid);
            if (t + 1 < NCHUNK) {
                float v[8];
                const int e[8] = {pe[0].x, pe[0].y, pe[0].z, pe[0].w,
                                  pe[1].x, pe[1].y, pe[1].z, pe[1].w};
                const float a[8] = {pa[0].x, pa[0].y, pa[0].z, pa[0].w,
                                    pa[1].x, pa[1].y, pa[1].z, pa[1].w};
#pragma unroll
                for (int p = 0; p < 8; p++)
                    v[p] = tf32r(a[p] * lds_f(lut + ((unsigned)e[p] << 2)));
                const unsigned o0 = sb + A_ST(t + 1) + (unsigned)arow * ROWB +
                                    (unsigned)ac0 * 4;
                STS128F(o0,      v[0], v[4], v[1], v[5]);
                STS128F(o0 + 16, v[2], v[6], v[3], v[7]);
            }
            if (t + 2 < NCHUNK) {
                const long src = rowbase + (((it + t + 2) & 15) << 6);
#pragma unroll
                for (int q = 0; q < 2; q++) {
                    pa[q] = __ldg((const float4*)(adj_b + src + q * 4));
                    pe[q] = __ldg((const int4*)(ea_b + src + q * 4));
                }
            }
            {
                const unsigned aSt = sb + A_ST(t), bSt = sb + B_ST(t);
#pragma unroll
                for (int ks = 0; ks < 8; ks++) {
                    const unsigned kb = (unsigned)ks * 32;
                    const uint2 a01 = lds_u64(aSt + aoff + kb);
                    const uint2 a23 = lds_u64(aSt + aoff + kb + 8 * ROWB);
                    const unsigned af[4] = {a01.x, a23.x, a01.y, a23.y};
#pragma unroll
                    for (int nt = 0; nt < 2; nt++) {
                        const uint2 bb = lds_u64(bSt + boff + (unsigned)nt * (8 * ROWB) + kb);
                        mma_tf32(acc[nt], af, bb.x, bb.y);
                    }
                }
            }
        }

        // ---- epilogue: add r (own rows, CTA-local), store out ----
        const int gid = lane >> 2, tig = lane & 3;
        const int grow = b * NPTS + i0 + wi * 16 + gid;
#pragma unroll
        for (int nt = 0; nt < 2; nt++) {
            const int  col  = wn * 16 + nt * 8 + tig * 2;
            const long idx0 = (long)grow * 64 + col;
            const long idx1 = (long)(grow + 8) * 64 + col;
            const float2 r0 = *(const float2*)&g_r[idx0];
            const float2 r1 = *(const float2*)&g_r[idx1];
            float2 o0, o1;
            o0.x = acc[nt][0] + r0.x; o0.y = acc[nt][1] + r0.y;
            o1.x = acc[nt][2] + r1.x; o1.y = acc[nt][3] + r1.y;
            *(float2*)&out[idx0] = o0;
            *(float2*)&out[idx1] = o1;
        }
    }

    // ---- reset protocol: 16th consumer of batch b zeroes flags + counter ----
    if (tid == 0) {
        const unsigned c = atomicAdd(&g_done[b], 1u);
        if (c == 15u) {
#pragma unroll
            for (int q = 0; q < 16; q++) g_flag[b * 16 + q] = 0u;
            __threadfence();
            g_done[b] = 0u;
        }
    }
}

// ===================== launch =====================
extern "C" void kernel_launch(void* const* d_in, const int* in_sizes, int n_in,
                              void* d_out, int out_size)
{
    const float* x      = (const float*)d_in[0];
    const float* adj    = (const float*)d_in[1];
    const int*   ea     = (const int*)d_in[2];
    const float* W_rel  = (const float*)d_in[3];
    const float* b_rel  = (const float*)d_in[4];
    const float* W_root = (const float*)d_in[5];
    const float* w_edge = (const float*)d_in[6];
    float* out = (float*)d_out;

    static bool attr_set = false;
    if (!attr_set) {
        cudaFuncSetAttribute(fused_kernel,
                             cudaFuncAttributeMaxDynamicSharedMemorySize, SMEM_DYN);
        attr_set = true;
    }

    fused_kernel<<<BATCH * 16, 512, SMEM_DYN>>>(x, W_rel, b_rel, W_root,
                                                adj, ea, w_edge, out);
}

// round 17
// speedup vs baseline: 1.1737x; 1.1737x over previous
#include <cuda_runtime.h>
#include <cuda_bf16.h>

#define BATCH 16
#define NPTS  1024
#define CDIM  64

// -------- scratch (__device__ globals, allocation-free rule) --------
__device__ float g_r[BATCH * NPTS * CDIM];    // x@W_root + b_rel (fp32)
__device__ float g_yT[BATCH * CDIM * NPTS];   // (x@W_rel)^T, tf32, sigma-permuted j

// ===================== helpers =====================
__device__ __forceinline__ unsigned smem_u32(const void* p) {
    unsigned a;
    asm("{ .reg .u64 t; cvta.to.shared.u64 t, %1; cvt.u32.u64 %0, t; }"
        : "=r"(a) : "l"(p));
    return a;
}
#define CP_ASYNC16(dst, src) \
    asm volatile("cp.async.cg.shared.global [%0], [%1], 16;" :: "r"(dst), "l"(src))
#define CP_COMMIT()  asm volatile("cp.async.commit_group;" ::: "memory")
#define STS128F(addr, r0, r1, r2, r3) \
    asm volatile("st.shared.v4.f32 [%0], {%1,%2,%3,%4};" \
                 :: "r"(addr), "f"(r0), "f"(r1), "f"(r2), "f"(r3) : "memory")
__device__ __forceinline__ void sts_f(unsigned a, float v) {
    asm volatile("st.shared.f32 [%0], %1;" :: "r"(a), "f"(v) : "memory");
}
__device__ __forceinline__ unsigned lds_u(unsigned a) {
    unsigned r;
    asm volatile("ld.shared.b32 %0, [%1];" : "=r"(r) : "r"(a));
    return r;
}
__device__ __forceinline__ uint2 lds_u64(unsigned a) {
    uint2 r;
    asm volatile("ld.shared.v2.b32 {%0,%1}, [%2];" : "=r"(r.x), "=r"(r.y) : "r"(a));
    return r;
}
__device__ __forceinline__ float4 lds128f(unsigned a) {
    float4 r;
    asm volatile("ld.shared.v4.f32 {%0,%1,%2,%3}, [%4];"
                 : "=f"(r.x), "=f"(r.y), "=f"(r.z), "=f"(r.w) : "r"(a));
    return r;
}
__device__ __forceinline__ float tf32r(float x) {
    unsigned u;
    asm("cvt.rna.tf32.f32 %0, %1;" : "=r"(u) : "f"(x));
    return __uint_as_float(u);
}
__device__ __forceinline__ void mma_tf32(float* d, const unsigned* a,
                                         unsigned b0, unsigned b1) {
    asm volatile("mma.sync.aligned.m16n8k8.row.col.f32.tf32.tf32.f32 "
                 "{%0,%1,%2,%3}, {%4,%5,%6,%7}, {%8,%9}, {%0,%1,%2,%3};"
                 : "+f"(d[0]), "+f"(d[1]), "+f"(d[2]), "+f"(d[3])
                 : "r"(a[0]), "r"(a[1]), "r"(a[2]), "r"(a[3]), "r"(b0), "r"(b1));
}
__device__ __forceinline__ float wsel(int e, float w0, float w1, float w2, float w3) {
    const float lo = (e == 0) ? w0 : w1;
    const float hi = (e == 2) ? w2 : w3;
    return (e < 2) ? lo : hi;
}

// ===================== Stage 1 (R13 verbatim: tf32 mma, 256 thr, sigma staging) ==
#define S1_XH  0
#define S1_XL  17408
#define S1_WRH 34816
#define S1_WRL 52224
#define S1_WOH 69632
#define S1_SMEM 87040

__global__ __launch_bounds__(256, 2) void stage1_kernel(
    const float* __restrict__ x, const float* __restrict__ W_rel,
    const float* __restrict__ b_rel, const float* __restrict__ W_root)
{
    extern __shared__ char smem_raw[];
    const unsigned sb = smem_u32(smem_raw);
    const int tid = threadIdx.x, lane = tid & 31, wid = tid >> 5;
    const int wm = wid & 3, wn2 = wid >> 2;
    const int row0 = blockIdx.x * 64;
    const int b = row0 >> 10, j0 = row0 & 1023;

    {
        const int r = tid >> 2, ch = (tid & 3) * 16;
        const float* src = x + (long)(row0 + r) * 64 + ch;
        const unsigned dh = sb + S1_XH + (unsigned)r * 272 + (unsigned)ch * 4;
#pragma unroll
        for (int q = 0; q < 4; q++) {
            float4 v = __ldg((const float4*)(src + q * 4));
            float hx = tf32r(v.x), hy = tf32r(v.y), hz = tf32r(v.z), hw = tf32r(v.w);
            STS128F(dh + q * 16, hx, hy, hz, hw);
            STS128F(dh + 17408 + q * 16, tf32r(v.x - hx), tf32r(v.y - hy),
                                          tf32r(v.z - hz), tf32r(v.w - hw));
        }
    }
#pragma unroll 4
    for (int i = 0; i < 16; i++) {
        const int idx = i * 256 + tid;
        const int k = idx >> 6, n = idx & 63;
        const float vr = __ldg(W_rel + idx);
        const float vo = __ldg(W_root + idx);
        const float hr = tf32r(vr);
        const unsigned ad = sb + (unsigned)n * 272 + (unsigned)k * 4;
        sts_f(ad + S1_WRH, hr);
        sts_f(ad + S1_WRL, tf32r(vr - hr));
        sts_f(ad + S1_WOH, tf32r(vo));
    }
    __syncthreads();

    const int gid = lane >> 2, tig = lane & 3;
    const unsigned aoff = sb + (unsigned)(wm * 16 + gid) * 272 + (unsigned)tig * 4;
    const unsigned bnb  = (unsigned)(wn2 * 32 + gid) * 272 + (unsigned)tig * 4;

    float acc[4][4] = {};
#pragma unroll
    for (int ks = 0; ks < 8; ks++) {
        const unsigned kb = (unsigned)ks * 32;
        unsigned ah[4], al[4];
        ah[0] = lds_u(aoff + kb);            ah[1] = lds_u(aoff + kb + 8 * 272);
        ah[2] = lds_u(aoff + kb + 16);       ah[3] = lds_u(aoff + kb + 8 * 272 + 16);
        al[0] = lds_u(aoff + 17408 + kb);    al[1] = lds_u(aoff + 17408 + kb + 8 * 272);
        al[2] = lds_u(aoff + 17408 + kb + 16); al[3] = lds_u(aoff + 17408 + kb + 8 * 272 + 16);
#pragma unroll
        for (int nf = 0; nf < 4; nf++) {
            const unsigned bo = sb + bnb + (unsigned)nf * 2176 + kb;
            const unsigned bh0 = lds_u(bo + S1_WRH), bh1 = lds_u(bo + S1_WRH + 16);
            const unsigned bl0 = lds_u(bo + S1_WRL), bl1 = lds_u(bo + S1_WRL + 16);
            mma_tf32(acc[nf], ah, bh0, bh1);
            mma_tf32(acc[nf], al, bh0, bh1);
            mma_tf32(acc[nf], ah, bl0, bl1);
        }
    }
    __syncthreads();

#pragma unroll
    for (int nf = 0; nf < 4; nf++)
#pragma unroll
        for (int q = 0; q < 4; q++) {
            const int c = wn2 * 32 + nf * 8 + tig * 2 + (q & 1);
            const int j = wm * 16 + gid + (q >> 1) * 8;
            const int jp = (j & ~7) | (((j & 3) << 1) | ((j >> 2) & 1));
            sts_f(sb + S1_XL + (unsigned)c * 272 + (unsigned)jp * 4, tf32r(acc[nf][q]));
        }

    float acc2[4][4] = {};
#pragma unroll
    for (int ks = 0; ks < 8; ks++) {
        const unsigned kb = (unsigned)ks * 32;
        unsigned ah[4];
        ah[0] = lds_u(aoff + kb);      ah[1] = lds_u(aoff + kb + 8 * 272);
        ah[2] = lds_u(aoff + kb + 16); ah[3] = lds_u(aoff + kb + 8 * 272 + 16);
#pragma unroll
        for (int nf = 0; nf < 4; nf++) {
            const unsigned bo = sb + S1_WOH + bnb + (unsigned)nf * 2176 + kb;
            mma_tf32(acc2[nf], ah, lds_u(bo), lds_u(bo + 16));
        }
    }
    __syncthreads();

    {
        const int c = tid >> 2, jh = (tid & 3) * 16;
        float* dst = g_yT + ((long)(b * 64 + c) << 10) + j0 + jh;
        const unsigned sa = sb + S1_XL + (unsigned)c * 272 + (unsigned)jh * 4;
#pragma unroll
        for (int q = 0; q < 4; q++) {
            float4 v = lds128f(sa + q * 16);
            *(float4*)(dst + q * 4) = v;
        }
    }
#pragma unroll
    for (int nf = 0; nf < 4; nf++) {
        const int col = wn2 * 32 + nf * 8 + tig * 2;
        const int grow = row0 + wm * 16 + gid;
        const float2 rb = *(const float2*)(b_rel + col);
        float2 o0, o1;
        o0.x = acc2[nf][0] + rb.x; o0.y = acc2[nf][1] + rb.y;
        o1.x = acc2[nf][2] + rb.x; o1.y = acc2[nf][3] + rb.y;
        *(float2*)&g_r[(long)grow * 64 + col] = o0;
        *(float2*)&g_r[(long)(grow + 8) * 64 + col] = o1;
    }
}

// ===================== Stage 2 (R12/R13 + register wsel, no SMEM LUT) ============
#define NCHUNK   16
#define ROWB     288
#define A_ST(t)  (((t) & 1) * 18432)
#define B_ST(t)  (36864 + ((t) % 3) * 18432)
#define SMEM_DYN 92160

__device__ __forceinline__ void issue_B(unsigned sbp, int j0,
                                        const float* __restrict__ yT_b, int tid) {
#pragma unroll
    for (int v = 0; v < 2; v++) {
        const int idx  = tid + v * 512;
        const int row  = idx >> 4;
        const int slot = idx & 15;
        CP_ASYNC16(sbp + (unsigned)row * ROWB + slot * 16,
                   yT_b + ((long)row << 10) + j0 + slot * 4);
    }
    CP_COMMIT();
}

__global__ __launch_bounds__(512, 2) void stage2_kernel(
    const float* __restrict__ adj, const int* __restrict__ ea,
    const float* __restrict__ w_edge, float* __restrict__ out)
{
    extern __shared__ char smem_raw[];
    const unsigned sb = smem_u32(smem_raw);

    const int tid = threadIdx.x, lane = tid & 31, wid = tid >> 5;
    const int wi = wid & 3, wn = wid >> 2;
    const int b  = blockIdx.x >> 4;
    const int i0 = (blockIdx.x & 15) * 64;

    const float* adj_b = adj + ((long)b << 20);
    const int*   ea_b  = ea  + ((long)b << 20);
    const float* yT_b  = g_yT + ((long)(b * 64) << 10);

    const float w0 = __ldg(w_edge + 0), w1 = __ldg(w_edge + 1),
                w2 = __ldg(w_edge + 2), w3 = __ldg(w_edge + 3);

    const int  arow = tid >> 3;
    const int  ac0  = (tid & 7) << 3;
    const long rowbase = (long)(i0 + arow) * NPTS + ac0;

    const unsigned aoff = (unsigned)(wi * 16 + (lane >> 2)) * ROWB +
                          (unsigned)(lane & 3) * 8;
    const unsigned boff = (unsigned)(wn * 16 + (lane >> 2)) * ROWB +
                          (unsigned)(lane & 3) * 8;

    float acc[2][4] = {};
    float4 pa[2]; int4 pe[2];

    issue_B(sb + B_ST(0), 0,  yT_b, tid);
    issue_B(sb + B_ST(1), 64, yT_b, tid);

#pragma unroll
    for (int q = 0; q < 2; q++) {
        pa[q] = __ldg((const float4*)(adj_b + rowbase + q * 4));
        pe[q] = __ldg((const int4*)(ea_b + rowbase + q * 4));
    }
    {
        float v[8];
        const int e[8] = {pe[0].x, pe[0].y, pe[0].z, pe[0].w,
                          pe[1].x, pe[1].y, pe[1].z, pe[1].w};
        const float a[8] = {pa[0].x, pa[0].y, pa[0].z, pa[0].w,
                            pa[1].x, pa[1].y, pa[1].z, pa[1].w};
#pragma unroll
        for (int p = 0; p < 8; p++)
            v[p] = tf32r(a[p] * wsel(e[p], w0, w1, w2, w3));
        const unsigned o0 = sb + A_ST(0) + (unsigned)arow * ROWB + (unsigned)ac0 * 4;
        STS128F(o0,      v[0], v[4], v[1], v[5]);   // sigma order
        STS128F(o0 + 16, v[2], v[6], v[3], v[7]);
    }
#pragma unroll
    for (int q = 0; q < 2; q++) {
        pa[q] = __ldg((const float4*)(adj_b + rowbase + 64 + q * 4));
        pe[q] = __ldg((const int4*)(ea_b + rowbase + 64 + q * 4));
    }

#pragma unroll 1
    for (int t = 0; t < NCHUNK; t++) {
        if (t < NCHUNK - 1) asm volatile("cp.async.wait_group 1;" ::: "memory");
        else                asm volatile("cp.async.wait_group 0;" ::: "memory");
        __syncthreads();
        if (t + 2 < NCHUNK)
            issue_B(sb + B_ST(t + 2), (t + 2) * 64, yT_b, tid);
        if (t + 1 < NCHUNK) {
            float v[8];
            const int e[8] = {pe[0].x, pe[0].y, pe[0].z, pe[0].w,
                              pe[1].x, pe[1].y, pe[1].z, pe[1].w};
            const float a[8] = {pa[0].x, pa[0].y, pa[0].z, pa[0].w,
                                pa[1].x, pa[1].y, pa[1].z, pa[1].w};
#pragma unroll
            for (int p = 0; p < 8; p++)
                v[p] = tf32r(a[p] * wsel(e[p], w0, w1, w2, w3));
            const unsigned o0 = sb + A_ST(t + 1) + (unsigned)arow * ROWB +
                                (unsigned)ac0 * 4;
            STS128F(o0,      v[0], v[4], v[1], v[5]);
            STS128F(o0 + 16, v[2], v[6], v[3], v[7]);
        }
        if (t + 2 < NCHUNK) {
            const long src = rowbase + (t + 2) * 64;
#pragma unroll
            for (int q = 0; q < 2; q++) {
                pa[q] = __ldg((const float4*)(adj_b + src + q * 4));
                pe[q] = __ldg((const int4*)(ea_b + src + q * 4));
            }
        }
        {
            const unsigned aSt = sb + A_ST(t), bSt = sb + B_ST(t);
#pragma unroll
            for (int ks = 0; ks < 8; ks++) {
                const unsigned kb = (unsigned)ks * 32;
                const uint2 a01 = lds_u64(aSt + aoff + kb);
                const uint2 a23 = lds_u64(aSt + aoff + kb + 8 * ROWB);
                const unsigned af[4] = {a01.x, a23.x, a01.y, a23.y};
#pragma unroll
                for (int nt = 0; nt < 2; nt++) {
                    const uint2 bb = lds_u64(bSt + boff + (unsigned)nt * (8 * ROWB) + kb);
                    mma_tf32(acc[nt], af, bb.x, bb.y);
                }
            }
        }
    }

    const int gid = lane >> 2, tig = lane & 3;
    const int grow = b * NPTS + i0 + wi * 16 + gid;
#pragma unroll
    for (int nt = 0; nt < 2; nt++) {
        const int  col  = wn * 16 + nt * 8 + tig * 2;
        const long idx0 = (long)grow * 64 + col;
        const long idx1 = (long)(grow + 8) * 64 + col;
        const float2 r0 = *(const float2*)&g_r[idx0];
        const float2 r1 = *(const float2*)&g_r[idx1];
        float2 o0, o1;
        o0.x = acc[nt][0] + r0.x; o0.y = acc[nt][1] + r0.y;
        o1.x = acc[nt][2] + r1.x; o1.y = acc[nt][3] + r1.y;
        *(float2*)&out[idx0] = o0;
        *(float2*)&out[idx1] = o1;
    }
}

// ===================== launch =====================
extern "C" void kernel_launch(void* const* d_in, const int* in_sizes, int n_in,
                              void* d_out, int out_size)
{
    const float* x      = (const float*)d_in[0];
    const float* adj    = (const float*)d_in[1];
    const int*   ea     = (const int*)d_in[2];
    const float* W_rel  = (const float*)d_in[3];
    const float* b_rel  = (const float*)d_in[4];
    const float* W_root = (const float*)d_in[5];
    const float* w_edge = (const float*)d_in[6];
    float* out = (float*)d_out;

    static bool attr_set = false;
    if (!attr_set) {
        cudaFuncSetAttribute(stage1_kernel,
                             cudaFuncAttributeMaxDynamicSharedMemorySize, S1_SMEM);
        cudaFuncSetAttribute(stage2_kernel,
                             cudaFuncAttributeMaxDynamicSharedMemorySize, SMEM_DYN);
        attr_set = true;
    }

    stage1_kernel<<<BATCH * 16, 256, S1_SMEM>>>(x, W_rel, b_rel, W_root);
    stage2_kernel<<<BATCH * 16, 512, SMEM_DYN>>>(adj, ea, w_edge, out);
}